// round 12
// baseline (speedup 1.0000x reference)
#include <cuda_runtime.h>
#include <math.h>

#define N_ATOMS 4096
#define NG      128
#define QKV_LD  768

// Scratch (no allocations allowed)
__device__ float g_qkv[N_ATOMS * QKV_LD];   // per row: [0:256)=Q [256:512)=K [512:768)=V
__device__ float g_segsum[NG * 256];        // per-group attention segment sums
__device__ float g_wct[256 * 256];          // Wct[f][j] = (Wo2 @ Wo1)^T
__device__ float g_bc[256];                 // bc = Wo2 @ bo1
__device__ int   g_off[NG + 1];             // group start offsets (sorted seg ids)
__device__ int   g_cnt[NG];                 // per-group completion counters (attn fusion)

__device__ __forceinline__ float to_tf32(float x) {
    asm("cvt.rna.tf32.f32 %0, %0;" : "+f"(x));
    return x;
}

__device__ __forceinline__ void mma_tf32(float c[4], const unsigned a[4], const unsigned b[2]) {
    asm volatile(
        "mma.sync.aligned.m16n8k8.row.col.f32.tf32.tf32.f32 "
        "{%0,%1,%2,%3}, {%4,%5,%6,%7}, {%8,%9}, {%0,%1,%2,%3};"
        : "+f"(c[0]), "+f"(c[1]), "+f"(c[2]), "+f"(c[3])
        : "r"(a[0]), "r"(a[1]), "r"(a[2]), "r"(a[3]), "r"(b[0]), "r"(b[1]));
}

__device__ __forceinline__ float silu(float v) {          // exact-ish (final layer)
    return __fdividef(v, 1.0f + __expf(-v));
}

__device__ __forceinline__ float silu_fast(float x) {     // 1 MUFU: x/2*(1+tanh(x/2))
    float h = 0.5f * x;
    float t;
    asm("tanh.approx.f32 %0, %1;" : "=f"(t) : "f"(h));
    return h + h * t;
}

// ---------------------------------------------------------------------------
// k1 mega-kernel (128 threads/block):  [R9 proven config]
//   blocks [0,384)   : TF32 QKV projection, BM=128 BN=64 BK=32
//   blocks [384,416) : fp32 Wct[f][j] = sum_k Wo1[k][f] * Wo2[j][k]
//   blocks [416,424) : bc[j] = Wo2[j,:].bo1 ; block 416: g_off + g_cnt reset
// ---------------------------------------------------------------------------
#define PROJ_BLOCKS 384
#define WC_BLOCKS   32
#define K1_BLOCKS   (PROJ_BLOCKS + WC_BLOCKS + 8)
#define PP          40

__global__ __launch_bounds__(128) void k1(
        const float* __restrict__ x,
        const float* __restrict__ Wq, const float* __restrict__ bq,
        const float* __restrict__ Wk, const float* __restrict__ bk,
        const float* __restrict__ Wv, const float* __restrict__ bv,
        const float* __restrict__ Wo1, const float* __restrict__ bo1,
        const float* __restrict__ Wo2, const int* __restrict__ seg)
{
    __shared__ float sh[7680];
    const int bid = blockIdx.x;
    const int tid = threadIdx.x;

    if (bid < PROJ_BLOCKS) {
        // ---------------- TF32 projection ----------------
        float (*As)[PP] = (float(*)[PP])sh;              // [128][40]
        float (*Bs)[PP] = (float(*)[PP])(sh + 128 * PP); // [64][40]

        const int warp = tid >> 5;
        const int lane = tid & 31;
        const int grp  = lane >> 2;
        const int tig  = lane & 3;
        const int wm   = warp >> 1;
        const int wn   = warp & 1;

        const int n0 = (bid / 12) * 128;
        const int j0 = (bid % 12) * 64;
        const int sel = j0 >> 8;
        const float* __restrict__ W = (sel == 0) ? Wq : (sel == 1 ? Wk : Wv);
        const float* __restrict__ b = (sel == 0) ? bq : (sel == 1 ? bk : bv);
        const int jl = j0 & 255;

        float c[4][4][4] = {};

        for (int k0 = 0; k0 < 256; k0 += 32) {
            #pragma unroll
            for (int it = 0; it < 4; it++) {
                int lin = tid + it * 128;          // 0..511
                int row = lin >> 2;                // 0..127
                int c8  = lin & 3;                 // 8-k group
                const float* src = &x[(n0 + row) * 256 + k0 + c8 * 8];
                float4 lo = *(const float4*)src;
                float4 hi = *(const float4*)(src + 4);
                float4 s0 = make_float4(to_tf32(lo.x), to_tf32(hi.x),
                                        to_tf32(lo.y), to_tf32(hi.y));
                float4 s1 = make_float4(to_tf32(lo.z), to_tf32(hi.z),
                                        to_tf32(lo.w), to_tf32(hi.w));
                *(float4*)&As[row][c8 * 8]     = s0;
                *(float4*)&As[row][c8 * 8 + 4] = s1;
            }
            #pragma unroll
            for (int it = 0; it < 2; it++) {
                int lin = tid + it * 128;
                int row = lin >> 2;
                int c8  = lin & 3;
                const float* src = &W[(jl + row) * 256 + k0 + c8 * 8];
                float4 lo = *(const float4*)src;
                float4 hi = *(const float4*)(src + 4);
                float4 s0 = make_float4(to_tf32(lo.x), to_tf32(hi.x),
                                        to_tf32(lo.y), to_tf32(hi.y));
                float4 s1 = make_float4(to_tf32(lo.z), to_tf32(hi.z),
                                        to_tf32(lo.w), to_tf32(hi.w));
                *(float4*)&Bs[row][c8 * 8]     = s0;
                *(float4*)&Bs[row][c8 * 8 + 4] = s1;
            }
            __syncthreads();

            #pragma unroll
            for (int ks = 0; ks < 4; ks++) {
                const int kp = ks * 8 + 2 * tig;
                unsigned bf[4][2];
                #pragma unroll
                for (int nt = 0; nt < 4; nt++) {
                    float2 pB = *(const float2*)&Bs[wn * 32 + nt * 8 + grp][kp];
                    bf[nt][0] = __float_as_uint(pB.x);
                    bf[nt][1] = __float_as_uint(pB.y);
                }
                #pragma unroll
                for (int mt = 0; mt < 4; mt++) {
                    int rb = wm * 64 + mt * 16 + grp;
                    float2 pA0 = *(const float2*)&As[rb    ][kp];
                    float2 pA1 = *(const float2*)&As[rb + 8][kp];
                    unsigned af[4];
                    af[0] = __float_as_uint(pA0.x);
                    af[1] = __float_as_uint(pA1.x);
                    af[2] = __float_as_uint(pA0.y);
                    af[3] = __float_as_uint(pA1.y);
                    #pragma unroll
                    for (int nt = 0; nt < 4; nt++)
                        mma_tf32(c[mt][nt], af, bf[nt]);
                }
            }
            __syncthreads();
        }

        #pragma unroll
        for (int mt = 0; mt < 4; mt++) {
            int r0 = n0 + wm * 64 + mt * 16 + grp;
            int r1 = r0 + 8;
            #pragma unroll
            for (int nt = 0; nt < 4; nt++) {
                int jj  = j0 + wn * 32 + nt * 8 + tig * 2;
                int jlb = jl + wn * 32 + nt * 8 + tig * 2;
                float b0 = b[jlb], b1 = b[jlb + 1];
                *(float2*)&g_qkv[r0 * QKV_LD + jj] = make_float2(c[mt][nt][0] + b0, c[mt][nt][1] + b1);
                *(float2*)&g_qkv[r1 * QKV_LD + jj] = make_float2(c[mt][nt][2] + b0, c[mt][nt][3] + b1);
            }
        }
    } else if (bid < PROJ_BLOCKS + WC_BLOCKS) {
        // ---------------- fp32 Wct tile: 32 f-rows x 64 j-cols ----------------
        float (*As)[36] = (float(*)[36])sh;
        float (*Bs)[68] = (float(*)[68])(sh + 32 * 36);

        const int t  = bid - PROJ_BLOCKS;
        const int f0 = (t >> 2) * 32;
        const int j0 = (t & 3) * 64;
        const int ti = tid >> 3;
        const int tj = tid & 7;

        float acc[2][8] = {};

        for (int k0 = 0; k0 < 256; k0 += 32) {
            #pragma unroll
            for (int it = 0; it < 2; it++) {
                int lin = tid + it * 128;
                int kk = lin >> 3;
                int fq = lin & 7;
                float4 a = *(const float4*)&Wo1[(k0 + kk) * 256 + f0 + fq * 4];
                *(float4*)&As[kk][fq * 4] = a;
            }
            #pragma unroll
            for (int it = 0; it < 4; it++) {
                int lin = tid + it * 128;
                int jj = lin >> 3;
                int kq = lin & 7;
                float4 w = *(const float4*)&Wo2[(j0 + jj) * 256 + k0 + kq * 4];
                Bs[kq * 4 + 0][jj] = w.x;
                Bs[kq * 4 + 1][jj] = w.y;
                Bs[kq * 4 + 2][jj] = w.z;
                Bs[kq * 4 + 3][jj] = w.w;
            }
            __syncthreads();
            #pragma unroll
            for (int kk = 0; kk < 32; kk++) {
                float2 a2 = *(const float2*)&As[kk][ti * 2];
                float4 b4a = *(const float4*)&Bs[kk][tj * 8];
                float4 b4b = *(const float4*)&Bs[kk][tj * 8 + 4];
                acc[0][0] += a2.x * b4a.x; acc[0][1] += a2.x * b4a.y;
                acc[0][2] += a2.x * b4a.z; acc[0][3] += a2.x * b4a.w;
                acc[0][4] += a2.x * b4b.x; acc[0][5] += a2.x * b4b.y;
                acc[0][6] += a2.x * b4b.z; acc[0][7] += a2.x * b4b.w;
                acc[1][0] += a2.y * b4a.x; acc[1][1] += a2.y * b4a.y;
                acc[1][2] += a2.y * b4a.z; acc[1][3] += a2.y * b4a.w;
                acc[1][4] += a2.y * b4b.x; acc[1][5] += a2.y * b4b.y;
                acc[1][6] += a2.y * b4b.z; acc[1][7] += a2.y * b4b.w;
            }
            __syncthreads();
        }
        #pragma unroll
        for (int u = 0; u < 2; u++)
            #pragma unroll
            for (int v = 0; v < 8; v++)
                g_wct[(f0 + ti * 2 + u) * 256 + j0 + tj * 8 + v] = acc[u][v];
    } else {
        // ------- bc[j] = Wo2[j,:].bo1 ; block 0: g_off + reset g_cnt -------
        const int bb   = bid - PROJ_BLOCKS - WC_BLOCKS;   // 0..7
        const int w    = tid >> 5;
        const int lane = tid & 31;
        #pragma unroll
        for (int u = 0; u < 8; u++) {
            int j = bb * 32 + w * 8 + u;
            float s = 0.0f;
            #pragma unroll
            for (int kc = 0; kc < 8; kc++) {
                int k = kc * 32 + lane;
                s += Wo2[j * 256 + k] * bo1[k];
            }
            #pragma unroll
            for (int off = 16; off; off >>= 1)
                s += __shfl_xor_sync(0xffffffffu, s, off);
            if (lane == 0) g_bc[j] = s;
        }
        if (bb == 0) {
            int g = tid;          // 0..127
            int lo = 0, hi = N_ATOMS;
            while (lo < hi) { int mid = (lo + hi) >> 1; if (seg[mid] < g) lo = mid + 1; else hi = mid; }
            g_off[g] = lo;
            g_cnt[g] = 0;
            if (tid == 0) g_off[NG] = N_ATOMS;
        }
    }
}

// ---------------------------------------------------------------------------
// Attention segment-sum + fused (last-block-wins) output projection.
// Block = (group, head), 256 threads = 8 warps (2x warp supply vs R11).
//   T[m] = sum_n silu(k_m . q_n)  — lane = m (k_m in regs), n split 8 ways
//   segsum slice -> global; 8th finishing block of group g computes
//   out[g][j] = silu( sum_f segsum[g][f]*Wct[f][j] + cnt*bc[j] + bo2[j] )
// ---------------------------------------------------------------------------
__global__ __launch_bounds__(256) void attn_kernel(
        const float* __restrict__ bo2, float* __restrict__ out)
{
    __shared__ float Ks[32][33];
    __shared__ float Vs[32][33];
    __shared__ float Qs[32][33];
    __shared__ float Tsh[8][32];
    __shared__ float Osh[8][32];
    __shared__ float a_sh[256];
    __shared__ int   s_last;

    const int g    = blockIdx.x;
    const int h    = blockIdx.y;
    const int tid  = threadIdx.x;
    const int w    = tid >> 5;         // 0..7
    const int lane = tid & 31;
    const int hb   = h * 32;

    const int start = g_off[g];
    const int end   = g_off[g + 1];
    const int L     = end - start;

    float out_acc = 0.0f;
    const float4 z4 = make_float4(0.f, 0.f, 0.f, 0.f);

    for (int mc = 0; mc < L; mc += 32) {
        const int lm = min(32, L - mc);
        // stage K,V: 256 float4 slots each, 1 per thread
        {
            int r  = tid >> 3;
            int c4 = tid & 7;
            float4 kv = (r < lm) ? *(const float4*)&g_qkv[(start + mc + r) * QKV_LD + 256 + hb + c4 * 4] : z4;
            float4 vv = (r < lm) ? *(const float4*)&g_qkv[(start + mc + r) * QKV_LD + 512 + hb + c4 * 4] : z4;
            Ks[r][c4 * 4 + 0] = kv.x; Ks[r][c4 * 4 + 1] = kv.y;
            Ks[r][c4 * 4 + 2] = kv.z; Ks[r][c4 * 4 + 3] = kv.w;
            Vs[r][c4 * 4 + 0] = vv.x; Vs[r][c4 * 4 + 1] = vv.y;
            Vs[r][c4 * 4 + 2] = vv.z; Vs[r][c4 * 4 + 3] = vv.w;
        }
        __syncthreads();

        float kreg[32];
        #pragma unroll
        for (int d = 0; d < 32; d++)
            kreg[d] = Ks[lane][d];

        float T = 0.0f;       // partial over this warp's n subset
        for (int nc = 0; nc < L; nc += 32) {
            const int ln = min(32, L - nc);
            {
                int r  = tid >> 3;
                int c4 = tid & 7;
                float4 qv = (r < ln) ? *(const float4*)&g_qkv[(start + nc + r) * QKV_LD + hb + c4 * 4] : z4;
                Qs[r][c4 * 4 + 0] = qv.x; Qs[r][c4 * 4 + 1] = qv.y;
                Qs[r][c4 * 4 + 2] = qv.z; Qs[r][c4 * 4 + 3] = qv.w;
            }
            __syncthreads();

            // warp w handles n in [w*4, min(w*4+4, ln))
            const int ncnt = max(0, min(4, ln - w * 4));
            for (int i = 0; i < ncnt; i++) {
                const int n = w * 4 + i;
                float d0 = 0.f, d1 = 0.f, d2 = 0.f, d3 = 0.f;
                #pragma unroll
                for (int d = 0; d < 8; d++) {
                    d0 += kreg[d     ] * Qs[n][d     ];
                    d1 += kreg[d +  8] * Qs[n][d +  8];
                    d2 += kreg[d + 16] * Qs[n][d + 16];
                    d3 += kreg[d + 24] * Qs[n][d + 24];
                }
                T += silu_fast((d0 + d1) + (d2 + d3));
            }
            __syncthreads();
        }

        Tsh[w][lane] = T;
        __syncthreads();

        // AV: warp w handles m in [w*4, w*4+4); T_tot[m] = sum_w' Tsh[w'][m]
        #pragma unroll
        for (int i = 0; i < 4; i++) {
            int m = w * 4 + i;
            float tm = Tsh[0][m] + Tsh[1][m] + Tsh[2][m] + Tsh[3][m]
                     + Tsh[4][m] + Tsh[5][m] + Tsh[6][m] + Tsh[7][m];
            out_acc += tm * Vs[m][lane];
        }
        __syncthreads();
    }

    Osh[w][lane] = out_acc;
    __syncthreads();
    if (w == 0) {
        float s = Osh[0][lane] + Osh[1][lane] + Osh[2][lane] + Osh[3][lane]
                + Osh[4][lane] + Osh[5][lane] + Osh[6][lane] + Osh[7][lane];
        g_segsum[g * 256 + hb + lane] = s;
    }

    // ---- last block of this group computes the output projection ----
    __threadfence();
    if (tid == 0) {
        int old = atomicAdd(&g_cnt[g], 1);
        s_last = (old == 7) ? 1 : 0;
    }
    __syncthreads();
    if (!s_last) return;

    __threadfence();    // acquire: make all 8 segsum slices visible
    a_sh[tid] = g_segsum[g * 256 + tid];
    __syncthreads();

    const float cnt = (float)L;
    float acc = 0.0f;
    #pragma unroll 8
    for (int f = 0; f < 256; f++)
        acc += a_sh[f] * g_wct[f * 256 + tid];

    out[g * 256 + tid] = silu(acc + cnt * g_bc[tid] + bo2[tid]);
}

// ---------------------------------------------------------------------------
extern "C" void kernel_launch(void* const* d_in, const int* in_sizes, int n_in,
                              void* d_out, int out_size)
{
    const float* x    = (const float*)d_in[0];
    const int*   elem = (const int*)d_in[1];
    const int*   seg  = elem + N_ATOMS;        // elem_index[1]
    const float* Wq   = (const float*)d_in[2];
    const float* bq   = (const float*)d_in[3];
    const float* Wk   = (const float*)d_in[4];
    const float* bk   = (const float*)d_in[5];
    const float* Wv   = (const float*)d_in[6];
    const float* bv   = (const float*)d_in[7];
    const float* Wo1  = (const float*)d_in[8];
    const float* bo1  = (const float*)d_in[9];
    const float* Wo2  = (const float*)d_in[10];
    const float* bo2  = (const float*)d_in[11];
    float* out = (float*)d_out;

    k1<<<K1_BLOCKS, 128>>>(x, Wq, bq, Wk, bk, Wv, bv, Wo1, bo1, Wo2, seg);
    attn_kernel<<<dim3(NG, 8), 256>>>(bo2, out);
}

// round 13
// speedup vs baseline: 1.0084x; 1.0084x over previous
#include <cuda_runtime.h>
#include <math.h>

#define N_ATOMS 4096
#define NG      128
#define QKV_LD  768

// Scratch (no allocations allowed)
__device__ float g_qkv[N_ATOMS * QKV_LD];   // per row: [0:256)=Q [256:512)=K [512:768)=V
__device__ float g_segsum[NG * 256];        // per-group attention segment sums (atomic)
__device__ float g_wct[256 * 256];          // Wct[f][j] = (Wo2 @ Wo1)^T
__device__ float g_bc[256];                 // bc = Wo2 @ bo1
__device__ int   g_off[NG + 1];             // group start offsets (sorted seg ids)
__device__ int   g_cnt[NG];                 // per-group completion counters (attn fusion)

__device__ __forceinline__ float to_tf32(float x) {
    asm("cvt.rna.tf32.f32 %0, %0;" : "+f"(x));
    return x;
}

__device__ __forceinline__ void mma_tf32(float c[4], const unsigned a[4], const unsigned b[2]) {
    asm volatile(
        "mma.sync.aligned.m16n8k8.row.col.f32.tf32.tf32.f32 "
        "{%0,%1,%2,%3}, {%4,%5,%6,%7}, {%8,%9}, {%0,%1,%2,%3};"
        : "+f"(c[0]), "+f"(c[1]), "+f"(c[2]), "+f"(c[3])
        : "r"(a[0]), "r"(a[1]), "r"(a[2]), "r"(a[3]), "r"(b[0]), "r"(b[1]));
}

__device__ __forceinline__ float silu(float v) {          // exact-ish (final layer)
    return __fdividef(v, 1.0f + __expf(-v));
}

__device__ __forceinline__ float silu_fast(float x) {     // 1 MUFU: x/2*(1+tanh(x/2))
    float h = 0.5f * x;
    float t;
    asm("tanh.approx.f32 %0, %1;" : "=f"(t) : "f"(h));
    return h + h * t;
}

// ---------------------------------------------------------------------------
// k1 mega-kernel (128 threads/block):  [R9 proven config]
//   blocks [0,384)   : TF32 QKV projection, BM=128 BN=64 BK=32
//   blocks [384,416) : fp32 Wct[f][j] = sum_k Wo1[k][f] * Wo2[j][k]
//   blocks [416,424) : bc[j] = Wo2[j,:].bo1 ; zero g_segsum ; blk 416: g_off
// ---------------------------------------------------------------------------
#define PROJ_BLOCKS 384
#define WC_BLOCKS   32
#define K1_BLOCKS   (PROJ_BLOCKS + WC_BLOCKS + 8)
#define PP          40

__global__ __launch_bounds__(128) void k1(
        const float* __restrict__ x,
        const float* __restrict__ Wq, const float* __restrict__ bq,
        const float* __restrict__ Wk, const float* __restrict__ bk,
        const float* __restrict__ Wv, const float* __restrict__ bv,
        const float* __restrict__ Wo1, const float* __restrict__ bo1,
        const float* __restrict__ Wo2, const int* __restrict__ seg)
{
    __shared__ float sh[7680];
    const int bid = blockIdx.x;
    const int tid = threadIdx.x;

    if (bid < PROJ_BLOCKS) {
        // ---------------- TF32 projection ----------------
        float (*As)[PP] = (float(*)[PP])sh;              // [128][40]
        float (*Bs)[PP] = (float(*)[PP])(sh + 128 * PP); // [64][40]

        const int warp = tid >> 5;
        const int lane = tid & 31;
        const int grp  = lane >> 2;
        const int tig  = lane & 3;
        const int wm   = warp >> 1;
        const int wn   = warp & 1;

        const int n0 = (bid / 12) * 128;
        const int j0 = (bid % 12) * 64;
        const int sel = j0 >> 8;
        const float* __restrict__ W = (sel == 0) ? Wq : (sel == 1 ? Wk : Wv);
        const float* __restrict__ b = (sel == 0) ? bq : (sel == 1 ? bk : bv);
        const int jl = j0 & 255;

        float c[4][4][4] = {};

        for (int k0 = 0; k0 < 256; k0 += 32) {
            #pragma unroll
            for (int it = 0; it < 4; it++) {
                int lin = tid + it * 128;          // 0..511
                int row = lin >> 2;                // 0..127
                int c8  = lin & 3;                 // 8-k group
                const float* src = &x[(n0 + row) * 256 + k0 + c8 * 8];
                float4 lo = *(const float4*)src;
                float4 hi = *(const float4*)(src + 4);
                float4 s0 = make_float4(to_tf32(lo.x), to_tf32(hi.x),
                                        to_tf32(lo.y), to_tf32(hi.y));
                float4 s1 = make_float4(to_tf32(lo.z), to_tf32(hi.z),
                                        to_tf32(lo.w), to_tf32(hi.w));
                *(float4*)&As[row][c8 * 8]     = s0;
                *(float4*)&As[row][c8 * 8 + 4] = s1;
            }
            #pragma unroll
            for (int it = 0; it < 2; it++) {
                int lin = tid + it * 128;
                int row = lin >> 2;
                int c8  = lin & 3;
                const float* src = &W[(jl + row) * 256 + k0 + c8 * 8];
                float4 lo = *(const float4*)src;
                float4 hi = *(const float4*)(src + 4);
                float4 s0 = make_float4(to_tf32(lo.x), to_tf32(hi.x),
                                        to_tf32(lo.y), to_tf32(hi.y));
                float4 s1 = make_float4(to_tf32(lo.z), to_tf32(hi.z),
                                        to_tf32(lo.w), to_tf32(hi.w));
                *(float4*)&Bs[row][c8 * 8]     = s0;
                *(float4*)&Bs[row][c8 * 8 + 4] = s1;
            }
            __syncthreads();

            #pragma unroll
            for (int ks = 0; ks < 4; ks++) {
                const int kp = ks * 8 + 2 * tig;
                unsigned bf[4][2];
                #pragma unroll
                for (int nt = 0; nt < 4; nt++) {
                    float2 pB = *(const float2*)&Bs[wn * 32 + nt * 8 + grp][kp];
                    bf[nt][0] = __float_as_uint(pB.x);
                    bf[nt][1] = __float_as_uint(pB.y);
                }
                #pragma unroll
                for (int mt = 0; mt < 4; mt++) {
                    int rb = wm * 64 + mt * 16 + grp;
                    float2 pA0 = *(const float2*)&As[rb    ][kp];
                    float2 pA1 = *(const float2*)&As[rb + 8][kp];
                    unsigned af[4];
                    af[0] = __float_as_uint(pA0.x);
                    af[1] = __float_as_uint(pA1.x);
                    af[2] = __float_as_uint(pA0.y);
                    af[3] = __float_as_uint(pA1.y);
                    #pragma unroll
                    for (int nt = 0; nt < 4; nt++)
                        mma_tf32(c[mt][nt], af, bf[nt]);
                }
            }
            __syncthreads();
        }

        #pragma unroll
        for (int mt = 0; mt < 4; mt++) {
            int r0 = n0 + wm * 64 + mt * 16 + grp;
            int r1 = r0 + 8;
            #pragma unroll
            for (int nt = 0; nt < 4; nt++) {
                int jj  = j0 + wn * 32 + nt * 8 + tig * 2;
                int jlb = jl + wn * 32 + nt * 8 + tig * 2;
                float b0 = b[jlb], b1 = b[jlb + 1];
                *(float2*)&g_qkv[r0 * QKV_LD + jj] = make_float2(c[mt][nt][0] + b0, c[mt][nt][1] + b1);
                *(float2*)&g_qkv[r1 * QKV_LD + jj] = make_float2(c[mt][nt][2] + b0, c[mt][nt][3] + b1);
            }
        }
    } else if (bid < PROJ_BLOCKS + WC_BLOCKS) {
        // ---------------- fp32 Wct tile: 32 f-rows x 64 j-cols ----------------
        float (*As)[36] = (float(*)[36])sh;
        float (*Bs)[68] = (float(*)[68])(sh + 32 * 36);

        const int t  = bid - PROJ_BLOCKS;
        const int f0 = (t >> 2) * 32;
        const int j0 = (t & 3) * 64;
        const int ti = tid >> 3;
        const int tj = tid & 7;

        float acc[2][8] = {};

        for (int k0 = 0; k0 < 256; k0 += 32) {
            #pragma unroll
            for (int it = 0; it < 2; it++) {
                int lin = tid + it * 128;
                int kk = lin >> 3;
                int fq = lin & 7;
                float4 a = *(const float4*)&Wo1[(k0 + kk) * 256 + f0 + fq * 4];
                *(float4*)&As[kk][fq * 4] = a;
            }
            #pragma unroll
            for (int it = 0; it < 4; it++) {
                int lin = tid + it * 128;
                int jj = lin >> 3;
                int kq = lin & 7;
                float4 w = *(const float4*)&Wo2[(j0 + jj) * 256 + k0 + kq * 4];
                Bs[kq * 4 + 0][jj] = w.x;
                Bs[kq * 4 + 1][jj] = w.y;
                Bs[kq * 4 + 2][jj] = w.z;
                Bs[kq * 4 + 3][jj] = w.w;
            }
            __syncthreads();
            #pragma unroll
            for (int kk = 0; kk < 32; kk++) {
                float2 a2 = *(const float2*)&As[kk][ti * 2];
                float4 b4a = *(const float4*)&Bs[kk][tj * 8];
                float4 b4b = *(const float4*)&Bs[kk][tj * 8 + 4];
                acc[0][0] += a2.x * b4a.x; acc[0][1] += a2.x * b4a.y;
                acc[0][2] += a2.x * b4a.z; acc[0][3] += a2.x * b4a.w;
                acc[0][4] += a2.x * b4b.x; acc[0][5] += a2.x * b4b.y;
                acc[0][6] += a2.x * b4b.z; acc[0][7] += a2.x * b4b.w;
                acc[1][0] += a2.y * b4a.x; acc[1][1] += a2.y * b4a.y;
                acc[1][2] += a2.y * b4a.z; acc[1][3] += a2.y * b4a.w;
                acc[1][4] += a2.y * b4b.x; acc[1][5] += a2.y * b4b.y;
                acc[1][6] += a2.y * b4b.z; acc[1][7] += a2.y * b4b.w;
            }
            __syncthreads();
        }
        #pragma unroll
        for (int u = 0; u < 2; u++)
            #pragma unroll
            for (int v = 0; v < 8; v++)
                g_wct[(f0 + ti * 2 + u) * 256 + j0 + tj * 8 + v] = acc[u][v];
    } else {
        // -- bc[j] = Wo2[j,:].bo1 ; zero g_segsum ; block 0: g_off + g_cnt --
        const int bb   = bid - PROJ_BLOCKS - WC_BLOCKS;   // 0..7
        const int w    = tid >> 5;
        const int lane = tid & 31;
        #pragma unroll
        for (int u = 0; u < 8; u++) {
            int j = bb * 32 + w * 8 + u;
            float s = 0.0f;
            #pragma unroll
            for (int kc = 0; kc < 8; kc++) {
                int k = kc * 32 + lane;
                s += Wo2[j * 256 + k] * bo1[k];
            }
            #pragma unroll
            for (int off = 16; off; off >>= 1)
                s += __shfl_xor_sync(0xffffffffu, s, off);
            if (lane == 0) g_bc[j] = s;
        }
        // zero segsum: 32768 floats / 8 blocks = 4096 per block (float4)
        {
            float4 z = make_float4(0.f, 0.f, 0.f, 0.f);
            #pragma unroll
            for (int it = 0; it < 8; it++)
                *(float4*)&g_segsum[bb * 4096 + it * 512 + tid * 4] = z;
        }
        if (bb == 0) {
            int g = tid;          // 0..127
            int lo = 0, hi = N_ATOMS;
            while (lo < hi) { int mid = (lo + hi) >> 1; if (seg[mid] < g) lo = mid + 1; else hi = mid; }
            g_off[g] = lo;
            g_cnt[g] = 0;
            if (tid == 0) g_off[NG] = N_ATOMS;
        }
    }
}

// ---------------------------------------------------------------------------
// Attention segment-sum + fused (last-block-wins) output projection.
// Block = (group, head, n-half); 128 threads = 4 warps. Grid 2048 blocks ->
// ~55 warps/SM available (2x R11) and halved per-block work for big-L tails.
//   Block (g,h,s) handles n-chunks nc ≡ s (mod 2):
//     T[m] = sum_{n in its chunks} silu(k_m . q_n)   (lane = m, k_m in regs)
//     partial out[d] = sum_m T[m] * v_m[d]  -> atomicAdd into g_segsum
//   16th finishing block of group g computes
//     out[g][j] = silu( sum_f segsum[g][f]*Wct[f][j] + cnt*bc[j] + bo2[j] )
// ---------------------------------------------------------------------------
__global__ __launch_bounds__(128) void attn_kernel(
        const float* __restrict__ bo2, float* __restrict__ out)
{
    __shared__ float Ks[32][33];
    __shared__ float Vs[32][33];
    __shared__ float Qs[32][33];
    __shared__ float Tsh[4][32];
    __shared__ float Osh[4][32];
    __shared__ float a_sh[256];
    __shared__ int   s_last;

    const int g    = blockIdx.x;
    const int h    = blockIdx.y;
    const int sp   = blockIdx.z;       // n-half: chunks nc ≡ sp (mod 2)
    const int tid  = threadIdx.x;
    const int w    = tid >> 5;
    const int lane = tid & 31;
    const int hb   = h * 32;

    const int start = g_off[g];
    const int end   = g_off[g + 1];
    const int L     = end - start;

    const float4 z4 = make_float4(0.f, 0.f, 0.f, 0.f);

    if (sp * 32 < L) {   // this half has n-work
        float out_acc = 0.0f;

        for (int mc = 0; mc < L; mc += 32) {
            const int lm = min(32, L - mc);
            #pragma unroll
            for (int it = 0; it < 2; it++) {
                int idx = tid + it * 128;
                int r   = idx >> 3;
                int c4  = idx & 7;
                float4 kv = (r < lm) ? *(const float4*)&g_qkv[(start + mc + r) * QKV_LD + 256 + hb + c4 * 4] : z4;
                float4 vv = (r < lm) ? *(const float4*)&g_qkv[(start + mc + r) * QKV_LD + 512 + hb + c4 * 4] : z4;
                Ks[r][c4 * 4 + 0] = kv.x; Ks[r][c4 * 4 + 1] = kv.y;
                Ks[r][c4 * 4 + 2] = kv.z; Ks[r][c4 * 4 + 3] = kv.w;
                Vs[r][c4 * 4 + 0] = vv.x; Vs[r][c4 * 4 + 1] = vv.y;
                Vs[r][c4 * 4 + 2] = vv.z; Vs[r][c4 * 4 + 3] = vv.w;
            }
            __syncthreads();

            float kreg[32];
            #pragma unroll
            for (int d = 0; d < 32; d++)
                kreg[d] = Ks[lane][d];

            float T = 0.0f;
            for (int nc = sp * 32; nc < L; nc += 64) {
                const int ln = min(32, L - nc);
                #pragma unroll
                for (int it = 0; it < 2; it++) {
                    int idx = tid + it * 128;
                    int r   = idx >> 3;
                    int c4  = idx & 7;
                    float4 qv = (r < ln) ? *(const float4*)&g_qkv[(start + nc + r) * QKV_LD + hb + c4 * 4] : z4;
                    Qs[r][c4 * 4 + 0] = qv.x; Qs[r][c4 * 4 + 1] = qv.y;
                    Qs[r][c4 * 4 + 2] = qv.z; Qs[r][c4 * 4 + 3] = qv.w;
                }
                __syncthreads();

                const int ncnt = max(0, min(8, ln - w * 8));
                for (int i = 0; i < ncnt; i++) {
                    const int n = w * 8 + i;
                    float d0 = 0.f, d1 = 0.f, d2 = 0.f, d3 = 0.f;
                    #pragma unroll
                    for (int d = 0; d < 8; d++) {
                        d0 += kreg[d     ] * Qs[n][d     ];
                        d1 += kreg[d +  8] * Qs[n][d +  8];
                        d2 += kreg[d + 16] * Qs[n][d + 16];
                        d3 += kreg[d + 24] * Qs[n][d + 24];
                    }
                    T += silu_fast((d0 + d1) + (d2 + d3));
                }
                __syncthreads();
            }

            Tsh[w][lane] = T;
            __syncthreads();

            #pragma unroll
            for (int i = 0; i < 8; i++) {
                int m = w * 8 + i;
                float tm = Tsh[0][m] + Tsh[1][m] + Tsh[2][m] + Tsh[3][m];
                out_acc += tm * Vs[m][lane];
            }
            __syncthreads();
        }

        Osh[w][lane] = out_acc;
        __syncthreads();
        if (w == 0) {
            float s = Osh[0][lane] + Osh[1][lane] + Osh[2][lane] + Osh[3][lane];
            atomicAdd(&g_segsum[g * 256 + hb + lane], s);
        }
    }

    // ---- last (16th) block of this group computes the output projection ----
    __threadfence();
    if (tid == 0) {
        int old = atomicAdd(&g_cnt[g], 1);
        s_last = (old == 15) ? 1 : 0;
    }
    __syncthreads();
    if (!s_last) return;

    __threadfence();    // acquire: make all segsum contributions visible
    {
        float2 s2 = *(const float2*)&g_segsum[g * 256 + tid * 2];
        a_sh[tid * 2]     = s2.x;
        a_sh[tid * 2 + 1] = s2.y;
    }
    __syncthreads();

    const float cnt = (float)L;
    float acc0 = 0.f, acc1 = 0.f;
    #pragma unroll 8
    for (int f = 0; f < 256; f++) {
        float av = a_sh[f];
        float2 w2 = *(const float2*)&g_wct[f * 256 + tid * 2];
        acc0 += av * w2.x;
        acc1 += av * w2.y;
    }
    float2 bc2  = *(const float2*)&g_bc[tid * 2];
    float2 bo22 = *(const float2*)&bo2[tid * 2];
    float r0 = acc0 + cnt * bc2.x + bo22.x;
    float r1 = acc1 + cnt * bc2.y + bo22.y;
    *(float2*)&out[g * 256 + tid * 2] = make_float2(silu(r0), silu(r1));
}

// ---------------------------------------------------------------------------
extern "C" void kernel_launch(void* const* d_in, const int* in_sizes, int n_in,
                              void* d_out, int out_size)
{
    const float* x    = (const float*)d_in[0];
    const int*   elem = (const int*)d_in[1];
    const int*   seg  = elem + N_ATOMS;        // elem_index[1]
    const float* Wq   = (const float*)d_in[2];
    const float* bq   = (const float*)d_in[3];
    const float* Wk   = (const float*)d_in[4];
    const float* bk   = (const float*)d_in[5];
    const float* Wv   = (const float*)d_in[6];
    const float* bv   = (const float*)d_in[7];
    const float* Wo1  = (const float*)d_in[8];
    const float* bo1  = (const float*)d_in[9];
    const float* Wo2  = (const float*)d_in[10];
    const float* bo2  = (const float*)d_in[11];
    float* out = (float*)d_out;

    k1<<<K1_BLOCKS, 128>>>(x, Wq, bq, Wk, bk, Wv, bv, Wo1, bo1, Wo2, seg);
    attn_kernel<<<dim3(NG, 8, 2), 128>>>(bo2, out);
}

// round 14
// speedup vs baseline: 1.0255x; 1.0170x over previous
#include <cuda_runtime.h>
#include <math.h>

#define N_ATOMS 4096
#define NG      128
#define QKV_LD  768

// Scratch (no allocations allowed)
__device__ float g_qkv[N_ATOMS * QKV_LD];   // per row: [0:256)=Q [256:512)=K [512:768)=V
__device__ float g_segsum[NG * 256];        // per-group attention segment sums
__device__ float g_wct[256 * 256];          // Wct[f][j] = (Wo2 @ Wo1)^T
__device__ float g_bc[256];                 // bc = Wo2 @ bo1
__device__ int   g_off[NG + 1];             // group start offsets (sorted seg ids)
__device__ int   g_cnt[NG];                 // per-group completion counters (attn fusion)

__device__ __forceinline__ float to_tf32(float x) {
    asm("cvt.rna.tf32.f32 %0, %0;" : "+f"(x));
    return x;
}

__device__ __forceinline__ void mma_tf32(float c[4], const unsigned a[4], const unsigned b[2]) {
    asm volatile(
        "mma.sync.aligned.m16n8k8.row.col.f32.tf32.tf32.f32 "
        "{%0,%1,%2,%3}, {%4,%5,%6,%7}, {%8,%9}, {%0,%1,%2,%3};"
        : "+f"(c[0]), "+f"(c[1]), "+f"(c[2]), "+f"(c[3])
        : "r"(a[0]), "r"(a[1]), "r"(a[2]), "r"(a[3]), "r"(b[0]), "r"(b[1]));
}

__device__ __forceinline__ float silu(float v) {          // exact-ish (final layer)
    return __fdividef(v, 1.0f + __expf(-v));
}

__device__ __forceinline__ float silu_fast(float x) {     // 1 MUFU: x/2*(1+tanh(x/2))
    float h = 0.5f * x;
    float t;
    asm("tanh.approx.f32 %0, %1;" : "=f"(t) : "f"(h));
    return h + h * t;
}

// ---------------------------------------------------------------------------
// k1 mega-kernel (128 threads/block):  [R9 proven config]
//   blocks [0,384)   : TF32 QKV projection, BM=128 BN=64 BK=32
//   blocks [384,416) : fp32 Wct[f][j] = sum_k Wo1[k][f] * Wo2[j][k]
//   blocks [416,424) : bc[j] = Wo2[j,:].bo1 ; block 416: g_off + g_cnt reset
// ---------------------------------------------------------------------------
#define PROJ_BLOCKS 384
#define WC_BLOCKS   32
#define K1_BLOCKS   (PROJ_BLOCKS + WC_BLOCKS + 8)
#define PP          40

__global__ __launch_bounds__(128) void k1(
        const float* __restrict__ x,
        const float* __restrict__ Wq, const float* __restrict__ bq,
        const float* __restrict__ Wk, const float* __restrict__ bk,
        const float* __restrict__ Wv, const float* __restrict__ bv,
        const float* __restrict__ Wo1, const float* __restrict__ bo1,
        const float* __restrict__ Wo2, const int* __restrict__ seg)
{
    __shared__ float sh[7680];
    const int bid = blockIdx.x;
    const int tid = threadIdx.x;

    if (bid < PROJ_BLOCKS) {
        // ---------------- TF32 projection ----------------
        float (*As)[PP] = (float(*)[PP])sh;              // [128][40]
        float (*Bs)[PP] = (float(*)[PP])(sh + 128 * PP); // [64][40]

        const int warp = tid >> 5;
        const int lane = tid & 31;
        const int grp  = lane >> 2;
        const int tig  = lane & 3;
        const int wm   = warp >> 1;
        const int wn   = warp & 1;

        const int n0 = (bid / 12) * 128;
        const int j0 = (bid % 12) * 64;
        const int sel = j0 >> 8;
        const float* __restrict__ W = (sel == 0) ? Wq : (sel == 1 ? Wk : Wv);
        const float* __restrict__ b = (sel == 0) ? bq : (sel == 1 ? bk : bv);
        const int jl = j0 & 255;

        float c[4][4][4] = {};

        for (int k0 = 0; k0 < 256; k0 += 32) {
            #pragma unroll
            for (int it = 0; it < 4; it++) {
                int lin = tid + it * 128;          // 0..511
                int row = lin >> 2;                // 0..127
                int c8  = lin & 3;                 // 8-k group
                const float* src = &x[(n0 + row) * 256 + k0 + c8 * 8];
                float4 lo = *(const float4*)src;
                float4 hi = *(const float4*)(src + 4);
                float4 s0 = make_float4(to_tf32(lo.x), to_tf32(hi.x),
                                        to_tf32(lo.y), to_tf32(hi.y));
                float4 s1 = make_float4(to_tf32(lo.z), to_tf32(hi.z),
                                        to_tf32(lo.w), to_tf32(hi.w));
                *(float4*)&As[row][c8 * 8]     = s0;
                *(float4*)&As[row][c8 * 8 + 4] = s1;
            }
            #pragma unroll
            for (int it = 0; it < 2; it++) {
                int lin = tid + it * 128;
                int row = lin >> 2;
                int c8  = lin & 3;
                const float* src = &W[(jl + row) * 256 + k0 + c8 * 8];
                float4 lo = *(const float4*)src;
                float4 hi = *(const float4*)(src + 4);
                float4 s0 = make_float4(to_tf32(lo.x), to_tf32(hi.x),
                                        to_tf32(lo.y), to_tf32(hi.y));
                float4 s1 = make_float4(to_tf32(lo.z), to_tf32(hi.z),
                                        to_tf32(lo.w), to_tf32(hi.w));
                *(float4*)&Bs[row][c8 * 8]     = s0;
                *(float4*)&Bs[row][c8 * 8 + 4] = s1;
            }
            __syncthreads();

            #pragma unroll
            for (int ks = 0; ks < 4; ks++) {
                const int kp = ks * 8 + 2 * tig;
                unsigned bf[4][2];
                #pragma unroll
                for (int nt = 0; nt < 4; nt++) {
                    float2 pB = *(const float2*)&Bs[wn * 32 + nt * 8 + grp][kp];
                    bf[nt][0] = __float_as_uint(pB.x);
                    bf[nt][1] = __float_as_uint(pB.y);
                }
                #pragma unroll
                for (int mt = 0; mt < 4; mt++) {
                    int rb = wm * 64 + mt * 16 + grp;
                    float2 pA0 = *(const float2*)&As[rb    ][kp];
                    float2 pA1 = *(const float2*)&As[rb + 8][kp];
                    unsigned af[4];
                    af[0] = __float_as_uint(pA0.x);
                    af[1] = __float_as_uint(pA1.x);
                    af[2] = __float_as_uint(pA0.y);
                    af[3] = __float_as_uint(pA1.y);
                    #pragma unroll
                    for (int nt = 0; nt < 4; nt++)
                        mma_tf32(c[mt][nt], af, bf[nt]);
                }
            }
            __syncthreads();
        }

        #pragma unroll
        for (int mt = 0; mt < 4; mt++) {
            int r0 = n0 + wm * 64 + mt * 16 + grp;
            int r1 = r0 + 8;
            #pragma unroll
            for (int nt = 0; nt < 4; nt++) {
                int jj  = j0 + wn * 32 + nt * 8 + tig * 2;
                int jlb = jl + wn * 32 + nt * 8 + tig * 2;
                float b0 = b[jlb], b1 = b[jlb + 1];
                *(float2*)&g_qkv[r0 * QKV_LD + jj] = make_float2(c[mt][nt][0] + b0, c[mt][nt][1] + b1);
                *(float2*)&g_qkv[r1 * QKV_LD + jj] = make_float2(c[mt][nt][2] + b0, c[mt][nt][3] + b1);
            }
        }
    } else if (bid < PROJ_BLOCKS + WC_BLOCKS) {
        // ---------------- fp32 Wct tile: 32 f-rows x 64 j-cols ----------------
        float (*As)[36] = (float(*)[36])sh;
        float (*Bs)[68] = (float(*)[68])(sh + 32 * 36);

        const int t  = bid - PROJ_BLOCKS;
        const int f0 = (t >> 2) * 32;
        const int j0 = (t & 3) * 64;
        const int ti = tid >> 3;
        const int tj = tid & 7;

        float acc[2][8] = {};

        for (int k0 = 0; k0 < 256; k0 += 32) {
            #pragma unroll
            for (int it = 0; it < 2; it++) {
                int lin = tid + it * 128;
                int kk = lin >> 3;
                int fq = lin & 7;
                float4 a = *(const float4*)&Wo1[(k0 + kk) * 256 + f0 + fq * 4];
                *(float4*)&As[kk][fq * 4] = a;
            }
            #pragma unroll
            for (int it = 0; it < 4; it++) {
                int lin = tid + it * 128;
                int jj = lin >> 3;
                int kq = lin & 7;
                float4 w = *(const float4*)&Wo2[(j0 + jj) * 256 + k0 + kq * 4];
                Bs[kq * 4 + 0][jj] = w.x;
                Bs[kq * 4 + 1][jj] = w.y;
                Bs[kq * 4 + 2][jj] = w.z;
                Bs[kq * 4 + 3][jj] = w.w;
            }
            __syncthreads();
            #pragma unroll
            for (int kk = 0; kk < 32; kk++) {
                float2 a2 = *(const float2*)&As[kk][ti * 2];
                float4 b4a = *(const float4*)&Bs[kk][tj * 8];
                float4 b4b = *(const float4*)&Bs[kk][tj * 8 + 4];
                acc[0][0] += a2.x * b4a.x; acc[0][1] += a2.x * b4a.y;
                acc[0][2] += a2.x * b4a.z; acc[0][3] += a2.x * b4a.w;
                acc[0][4] += a2.x * b4b.x; acc[0][5] += a2.x * b4b.y;
                acc[0][6] += a2.x * b4b.z; acc[0][7] += a2.x * b4b.w;
                acc[1][0] += a2.y * b4a.x; acc[1][1] += a2.y * b4a.y;
                acc[1][2] += a2.y * b4a.z; acc[1][3] += a2.y * b4a.w;
                acc[1][4] += a2.y * b4b.x; acc[1][5] += a2.y * b4b.y;
                acc[1][6] += a2.y * b4b.z; acc[1][7] += a2.y * b4b.w;
            }
            __syncthreads();
        }
        #pragma unroll
        for (int u = 0; u < 2; u++)
            #pragma unroll
            for (int v = 0; v < 8; v++)
                g_wct[(f0 + ti * 2 + u) * 256 + j0 + tj * 8 + v] = acc[u][v];
    } else {
        // ------- bc[j] = Wo2[j,:].bo1 ; block 0: g_off + reset g_cnt -------
        const int bb   = bid - PROJ_BLOCKS - WC_BLOCKS;   // 0..7
        const int w    = tid >> 5;
        const int lane = tid & 31;
        #pragma unroll
        for (int u = 0; u < 8; u++) {
            int j = bb * 32 + w * 8 + u;
            float s = 0.0f;
            #pragma unroll
            for (int kc = 0; kc < 8; kc++) {
                int k = kc * 32 + lane;
                s += Wo2[j * 256 + k] * bo1[k];
            }
            #pragma unroll
            for (int off = 16; off; off >>= 1)
                s += __shfl_xor_sync(0xffffffffu, s, off);
            if (lane == 0) g_bc[j] = s;
        }
        if (bb == 0) {
            int g = tid;          // 0..127
            int lo = 0, hi = N_ATOMS;
            while (lo < hi) { int mid = (lo + hi) >> 1; if (seg[mid] < g) lo = mid + 1; else hi = mid; }
            g_off[g] = lo;
            g_cnt[g] = 0;
            if (tid == 0) g_off[NG] = N_ATOMS;
        }
    }
}

// ---------------------------------------------------------------------------
// Attention segment-sum + fused (last-block-wins) output projection.
// Block = (group, head); 128 threads = 4 warps. 64-row super-tiles:
// K/V/Q staged as 64x32 slabs (zero-padded) -> high-MLP LDG bursts and ~4
// barriers per typical (L<=64) block instead of ~10.
//   pass A: lane=m in [0,32), k_m in regs; pass B: m in [32,64) if lm>32.
//   n and AV-m split by stride-4 interleave for balance at any L.
// ---------------------------------------------------------------------------
__global__ __launch_bounds__(128) void attn_kernel(
        const float* __restrict__ bo2, float* __restrict__ out)
{
    __shared__ float Ks[64][33];
    __shared__ float Vs[64][33];
    __shared__ float Qs[64][33];
    __shared__ float Tsh[4][64];
    __shared__ float Osh[4][32];
    __shared__ float a_sh[256];
    __shared__ int   s_last;

    const int g    = blockIdx.x;
    const int h    = blockIdx.y;
    const int tid  = threadIdx.x;
    const int w    = tid >> 5;
    const int lane = tid & 31;
    const int hb   = h * 32;

    const int start = __ldg(&g_off[g]);
    const int end   = __ldg(&g_off[g + 1]);
    const int L     = end - start;

    const float4 z4 = make_float4(0.f, 0.f, 0.f, 0.f);
    float out_acc = 0.0f;

    for (int mc = 0; mc < L; mc += 64) {
        const int lm = min(64, L - mc);
        if (mc > 0) __syncthreads();          // prior Vs/Tsh readers done
        // stage K,V slabs: 512 float4 each, 4 per thread, high MLP
        #pragma unroll
        for (int it = 0; it < 4; it++) {
            int idx = tid + it * 128;          // 0..511
            int r   = idx >> 3;                // 0..63
            int c4  = idx & 7;
            float4 kv = (r < lm) ? *(const float4*)&g_qkv[(start + mc + r) * QKV_LD + 256 + hb + c4 * 4] : z4;
            float4 vv = (r < lm) ? *(const float4*)&g_qkv[(start + mc + r) * QKV_LD + 512 + hb + c4 * 4] : z4;
            Ks[r][c4 * 4 + 0] = kv.x; Ks[r][c4 * 4 + 1] = kv.y;
            Ks[r][c4 * 4 + 2] = kv.z; Ks[r][c4 * 4 + 3] = kv.w;
            Vs[r][c4 * 4 + 0] = vv.x; Vs[r][c4 * 4 + 1] = vv.y;
            Vs[r][c4 * 4 + 2] = vv.z; Vs[r][c4 * 4 + 3] = vv.w;
        }

        float T0 = 0.0f, T1 = 0.0f;
        for (int nc = 0; nc < L; nc += 64) {
            const int ln = min(64, L - nc);
            if (nc > 0) __syncthreads();      // prior Qs readers done
            #pragma unroll
            for (int it = 0; it < 4; it++) {
                int idx = tid + it * 128;
                int r   = idx >> 3;
                int c4  = idx & 7;
                float4 qv = (r < ln) ? *(const float4*)&g_qkv[(start + nc + r) * QKV_LD + hb + c4 * 4] : z4;
                Qs[r][c4 * 4 + 0] = qv.x; Qs[r][c4 * 4 + 1] = qv.y;
                Qs[r][c4 * 4 + 2] = qv.z; Qs[r][c4 * 4 + 3] = qv.w;
            }
            __syncthreads();                  // K/V (first iter) + Q staged

            const int ncnt = (ln - w + 3) >> 2;    // n = w + 4i, n < ln
            // pass A: m = lane
            {
                float kreg[32];
                #pragma unroll
                for (int d = 0; d < 32; d++)
                    kreg[d] = Ks[lane][d];
                for (int i = 0; i < ncnt; i++) {
                    const int n = w + i * 4;
                    float d0 = 0.f, d1 = 0.f, d2 = 0.f, d3 = 0.f;
                    #pragma unroll
                    for (int d = 0; d < 8; d++) {
                        d0 += kreg[d     ] * Qs[n][d     ];
                        d1 += kreg[d +  8] * Qs[n][d +  8];
                        d2 += kreg[d + 16] * Qs[n][d + 16];
                        d3 += kreg[d + 24] * Qs[n][d + 24];
                    }
                    T0 += silu_fast((d0 + d1) + (d2 + d3));
                }
            }
            // pass B: m = lane + 32 (only when this m-slab half is real)
            if (lm > 32) {
                float kreg[32];
                #pragma unroll
                for (int d = 0; d < 32; d++)
                    kreg[d] = Ks[lane + 32][d];
                for (int i = 0; i < ncnt; i++) {
                    const int n = w + i * 4;
                    float d0 = 0.f, d1 = 0.f, d2 = 0.f, d3 = 0.f;
                    #pragma unroll
                    for (int d = 0; d < 8; d++) {
                        d0 += kreg[d     ] * Qs[n][d     ];
                        d1 += kreg[d +  8] * Qs[n][d +  8];
                        d2 += kreg[d + 16] * Qs[n][d + 16];
                        d3 += kreg[d + 24] * Qs[n][d + 24];
                    }
                    T1 += silu_fast((d0 + d1) + (d2 + d3));
                }
            }
        }

        Tsh[w][lane]      = T0;
        Tsh[w][lane + 32] = T1;
        __syncthreads();

        // AV: m = w + 4i; T_tot[m] = sum_w' Tsh[w'][m]
        const int icnt = (lm > 32) ? 16 : 8;
        for (int i = 0; i < icnt; i++) {
            int m = w + i * 4;
            float tm = Tsh[0][m] + Tsh[1][m] + Tsh[2][m] + Tsh[3][m];
            out_acc += tm * Vs[m][lane];
        }
    }

    __syncthreads();
    Osh[w][lane] = out_acc;
    __syncthreads();
    if (w == 0)
        g_segsum[g * 256 + hb + lane] =
            Osh[0][lane] + Osh[1][lane] + Osh[2][lane] + Osh[3][lane];

    // ---- last block of this group computes the output projection ----
    __threadfence();
    if (tid == 0) {
        int old = atomicAdd(&g_cnt[g], 1);
        s_last = (old == 7) ? 1 : 0;
    }
    __syncthreads();
    if (!s_last) return;

    __threadfence();    // acquire: make all 8 segsum slices visible
    {
        float2 s2 = *(const float2*)&g_segsum[g * 256 + tid * 2];
        a_sh[tid * 2]     = s2.x;
        a_sh[tid * 2 + 1] = s2.y;
    }
    __syncthreads();

    const float cnt = (float)L;
    float acc0 = 0.f, acc1 = 0.f;
    #pragma unroll 8
    for (int f = 0; f < 256; f++) {
        float av = a_sh[f];
        float2 w2 = *(const float2*)&g_wct[f * 256 + tid * 2];
        acc0 += av * w2.x;
        acc1 += av * w2.y;
    }
    float2 bc2  = *(const float2*)&g_bc[tid * 2];
    float2 bo22 = *(const float2*)&bo2[tid * 2];
    float r0 = acc0 + cnt * bc2.x + bo22.x;
    float r1 = acc1 + cnt * bc2.y + bo22.y;
    *(float2*)&out[g * 256 + tid * 2] = make_float2(silu(r0), silu(r1));
}

// ---------------------------------------------------------------------------
extern "C" void kernel_launch(void* const* d_in, const int* in_sizes, int n_in,
                              void* d_out, int out_size)
{
    const float* x    = (const float*)d_in[0];
    const int*   elem = (const int*)d_in[1];
    const int*   seg  = elem + N_ATOMS;        // elem_index[1]
    const float* Wq   = (const float*)d_in[2];
    const float* bq   = (const float*)d_in[3];
    const float* Wk   = (const float*)d_in[4];
    const float* bk   = (const float*)d_in[5];
    const float* Wv   = (const float*)d_in[6];
    const float* bv   = (const float*)d_in[7];
    const float* Wo1  = (const float*)d_in[8];
    const float* bo1  = (const float*)d_in[9];
    const float* Wo2  = (const float*)d_in[10];
    const float* bo2  = (const float*)d_in[11];
    float* out = (float*)d_out;

    k1<<<K1_BLOCKS, 128>>>(x, Wq, bq, Wk, bk, Wv, bv, Wo1, bo1, Wo2, seg);
    attn_kernel<<<dim3(NG, 8), 128>>>(bo2, out);
}

// round 15
// speedup vs baseline: 1.1278x; 1.0997x over previous
#include <cuda_runtime.h>
#include <math.h>

#define N_ATOMS 4096
#define NG      128
#define QKV_LD  768

// Scratch (no allocations allowed)
__device__ float g_qkv[N_ATOMS * QKV_LD];   // per row: [0:256)=Q [256:512)=K [512:768)=V
__device__ float g_segsum[NG * 256];        // per-group attention segment sums
__device__ float g_wct[256 * 256];          // Wct[f][j] = (Wo2 @ Wo1)^T
__device__ float g_bc[256];                 // bc = Wo2 @ bo1
__device__ int   g_off[NG + 1];             // group start offsets (sorted seg ids)
__device__ int   g_cnt[NG];                 // per-group completion counters (attn fusion)

__device__ __forceinline__ float to_tf32(float x) {
    asm("cvt.rna.tf32.f32 %0, %0;" : "+f"(x));
    return x;
}

__device__ __forceinline__ void mma_tf32(float c[4], const unsigned a[4], const unsigned b[2]) {
    asm volatile(
        "mma.sync.aligned.m16n8k8.row.col.f32.tf32.tf32.f32 "
        "{%0,%1,%2,%3}, {%4,%5,%6,%7}, {%8,%9}, {%0,%1,%2,%3};"
        : "+f"(c[0]), "+f"(c[1]), "+f"(c[2]), "+f"(c[3])
        : "r"(a[0]), "r"(a[1]), "r"(a[2]), "r"(a[3]), "r"(b[0]), "r"(b[1]));
}

__device__ __forceinline__ float silu(float v) {          // exact-ish (final layer)
    return __fdividef(v, 1.0f + __expf(-v));
}

__device__ __forceinline__ float silu_fast(float x) {     // 1 MUFU: x/2*(1+tanh(x/2))
    float h = 0.5f * x;
    float t;
    asm("tanh.approx.f32 %0, %1;" : "=f"(t) : "f"(h));
    return h + h * t;
}

// ---------------------------------------------------------------------------
// k1 mega-kernel (128 threads/block):  [R9 proven config, unchanged]
//   blocks [0,384)   : TF32 QKV projection, BM=128 BN=64 BK=32
//   blocks [384,416) : fp32 Wct[f][j] = sum_k Wo1[k][f] * Wo2[j][k]
//   blocks [416,424) : bc[j] = Wo2[j,:].bo1 ; block 416: g_off + g_cnt reset
// ---------------------------------------------------------------------------
#define PROJ_BLOCKS 384
#define WC_BLOCKS   32
#define K1_BLOCKS   (PROJ_BLOCKS + WC_BLOCKS + 8)
#define PP          40

__global__ __launch_bounds__(128) void k1(
        const float* __restrict__ x,
        const float* __restrict__ Wq, const float* __restrict__ bq,
        const float* __restrict__ Wk, const float* __restrict__ bk,
        const float* __restrict__ Wv, const float* __restrict__ bv,
        const float* __restrict__ Wo1, const float* __restrict__ bo1,
        const float* __restrict__ Wo2, const int* __restrict__ seg)
{
    __shared__ float sh[7680];
    const int bid = blockIdx.x;
    const int tid = threadIdx.x;

    if (bid < PROJ_BLOCKS) {
        float (*As)[PP] = (float(*)[PP])sh;              // [128][40]
        float (*Bs)[PP] = (float(*)[PP])(sh + 128 * PP); // [64][40]

        const int warp = tid >> 5;
        const int lane = tid & 31;
        const int grp  = lane >> 2;
        const int tig  = lane & 3;
        const int wm   = warp >> 1;
        const int wn   = warp & 1;

        const int n0 = (bid / 12) * 128;
        const int j0 = (bid % 12) * 64;
        const int sel = j0 >> 8;
        const float* __restrict__ W = (sel == 0) ? Wq : (sel == 1 ? Wk : Wv);
        const float* __restrict__ b = (sel == 0) ? bq : (sel == 1 ? bk : bv);
        const int jl = j0 & 255;

        float c[4][4][4] = {};

        for (int k0 = 0; k0 < 256; k0 += 32) {
            #pragma unroll
            for (int it = 0; it < 4; it++) {
                int lin = tid + it * 128;
                int row = lin >> 2;
                int c8  = lin & 3;
                const float* src = &x[(n0 + row) * 256 + k0 + c8 * 8];
                float4 lo = *(const float4*)src;
                float4 hi = *(const float4*)(src + 4);
                float4 s0 = make_float4(to_tf32(lo.x), to_tf32(hi.x),
                                        to_tf32(lo.y), to_tf32(hi.y));
                float4 s1 = make_float4(to_tf32(lo.z), to_tf32(hi.z),
                                        to_tf32(lo.w), to_tf32(hi.w));
                *(float4*)&As[row][c8 * 8]     = s0;
                *(float4*)&As[row][c8 * 8 + 4] = s1;
            }
            #pragma unroll
            for (int it = 0; it < 2; it++) {
                int lin = tid + it * 128;
                int row = lin >> 2;
                int c8  = lin & 3;
                const float* src = &W[(jl + row) * 256 + k0 + c8 * 8];
                float4 lo = *(const float4*)src;
                float4 hi = *(const float4*)(src + 4);
                float4 s0 = make_float4(to_tf32(lo.x), to_tf32(hi.x),
                                        to_tf32(lo.y), to_tf32(hi.y));
                float4 s1 = make_float4(to_tf32(lo.z), to_tf32(hi.z),
                                        to_tf32(lo.w), to_tf32(hi.w));
                *(float4*)&Bs[row][c8 * 8]     = s0;
                *(float4*)&Bs[row][c8 * 8 + 4] = s1;
            }
            __syncthreads();

            #pragma unroll
            for (int ks = 0; ks < 4; ks++) {
                const int kp = ks * 8 + 2 * tig;
                unsigned bf[4][2];
                #pragma unroll
                for (int nt = 0; nt < 4; nt++) {
                    float2 pB = *(const float2*)&Bs[wn * 32 + nt * 8 + grp][kp];
                    bf[nt][0] = __float_as_uint(pB.x);
                    bf[nt][1] = __float_as_uint(pB.y);
                }
                #pragma unroll
                for (int mt = 0; mt < 4; mt++) {
                    int rb = wm * 64 + mt * 16 + grp;
                    float2 pA0 = *(const float2*)&As[rb    ][kp];
                    float2 pA1 = *(const float2*)&As[rb + 8][kp];
                    unsigned af[4];
                    af[0] = __float_as_uint(pA0.x);
                    af[1] = __float_as_uint(pA1.x);
                    af[2] = __float_as_uint(pA0.y);
                    af[3] = __float_as_uint(pA1.y);
                    #pragma unroll
                    for (int nt = 0; nt < 4; nt++)
                        mma_tf32(c[mt][nt], af, bf[nt]);
                }
            }
            __syncthreads();
        }

        #pragma unroll
        for (int mt = 0; mt < 4; mt++) {
            int r0 = n0 + wm * 64 + mt * 16 + grp;
            int r1 = r0 + 8;
            #pragma unroll
            for (int nt = 0; nt < 4; nt++) {
                int jj  = j0 + wn * 32 + nt * 8 + tig * 2;
                int jlb = jl + wn * 32 + nt * 8 + tig * 2;
                float b0 = b[jlb], b1 = b[jlb + 1];
                *(float2*)&g_qkv[r0 * QKV_LD + jj] = make_float2(c[mt][nt][0] + b0, c[mt][nt][1] + b1);
                *(float2*)&g_qkv[r1 * QKV_LD + jj] = make_float2(c[mt][nt][2] + b0, c[mt][nt][3] + b1);
            }
        }
    } else if (bid < PROJ_BLOCKS + WC_BLOCKS) {
        float (*As)[36] = (float(*)[36])sh;
        float (*Bs)[68] = (float(*)[68])(sh + 32 * 36);

        const int t  = bid - PROJ_BLOCKS;
        const int f0 = (t >> 2) * 32;
        const int j0 = (t & 3) * 64;
        const int ti = tid >> 3;
        const int tj = tid & 7;

        float acc[2][8] = {};

        for (int k0 = 0; k0 < 256; k0 += 32) {
            #pragma unroll
            for (int it = 0; it < 2; it++) {
                int lin = tid + it * 128;
                int kk = lin >> 3;
                int fq = lin & 7;
                float4 a = *(const float4*)&Wo1[(k0 + kk) * 256 + f0 + fq * 4];
                *(float4*)&As[kk][fq * 4] = a;
            }
            #pragma unroll
            for (int it = 0; it < 4; it++) {
                int lin = tid + it * 128;
                int jj = lin >> 3;
                int kq = lin & 7;
                float4 w = *(const float4*)&Wo2[(j0 + jj) * 256 + k0 + kq * 4];
                Bs[kq * 4 + 0][jj] = w.x;
                Bs[kq * 4 + 1][jj] = w.y;
                Bs[kq * 4 + 2][jj] = w.z;
                Bs[kq * 4 + 3][jj] = w.w;
            }
            __syncthreads();
            #pragma unroll
            for (int kk = 0; kk < 32; kk++) {
                float2 a2 = *(const float2*)&As[kk][ti * 2];
                float4 b4a = *(const float4*)&Bs[kk][tj * 8];
                float4 b4b = *(const float4*)&Bs[kk][tj * 8 + 4];
                acc[0][0] += a2.x * b4a.x; acc[0][1] += a2.x * b4a.y;
                acc[0][2] += a2.x * b4a.z; acc[0][3] += a2.x * b4a.w;
                acc[0][4] += a2.x * b4b.x; acc[0][5] += a2.x * b4b.y;
                acc[0][6] += a2.x * b4b.z; acc[0][7] += a2.x * b4b.w;
                acc[1][0] += a2.y * b4a.x; acc[1][1] += a2.y * b4a.y;
                acc[1][2] += a2.y * b4a.z; acc[1][3] += a2.y * b4a.w;
                acc[1][4] += a2.y * b4b.x; acc[1][5] += a2.y * b4b.y;
                acc[1][6] += a2.y * b4b.z; acc[1][7] += a2.y * b4b.w;
            }
            __syncthreads();
        }
        #pragma unroll
        for (int u = 0; u < 2; u++)
            #pragma unroll
            for (int v = 0; v < 8; v++)
                g_wct[(f0 + ti * 2 + u) * 256 + j0 + tj * 8 + v] = acc[u][v];
    } else {
        const int bb   = bid - PROJ_BLOCKS - WC_BLOCKS;   // 0..7
        const int w    = tid >> 5;
        const int lane = tid & 31;
        #pragma unroll
        for (int u = 0; u < 8; u++) {
            int j = bb * 32 + w * 8 + u;
            float s = 0.0f;
            #pragma unroll
            for (int kc = 0; kc < 8; kc++) {
                int k = kc * 32 + lane;
                s += Wo2[j * 256 + k] * bo1[k];
            }
            #pragma unroll
            for (int off = 16; off; off >>= 1)
                s += __shfl_xor_sync(0xffffffffu, s, off);
            if (lane == 0) g_bc[j] = s;
        }
        if (bb == 0) {
            int g = tid;          // 0..127
            int lo = 0, hi = N_ATOMS;
            while (lo < hi) { int mid = (lo + hi) >> 1; if (seg[mid] < g) lo = mid + 1; else hi = mid; }
            g_off[g] = lo;
            g_cnt[g] = 0;
            if (tid == 0) g_off[NG] = N_ATOMS;
        }
    }
}

// ---------------------------------------------------------------------------
// MMA attention + fused (last-block-wins) output projection.
// Block = (group, head); 128 threads = 4 warps.
//   S(32x32) = K_chunk . Q_chunk^T via tf32 mma m16n8k8 (proj frag layout):
//     warp w computes S cols [w*8, w*8+8): 2 m-tiles x 4 k-steps = 8 mma.
//   T[m] += row-sums of silu(S) straight from the C layout:
//     c0,c1 = S[grp][2tig..], c2,c3 = S[grp+8][2tig..]; 2 shfl_xor finish 8 cols.
//   AV: out[d] += T[m] * V[m][d].  Zero-padding exact (silu(0)=0, V pad=0).
// ---------------------------------------------------------------------------
__global__ __launch_bounds__(128) void attn_kernel(
        const float* __restrict__ bo2, float* __restrict__ out)
{
    __shared__ float Ks[32][PP];     // tf32, k-pair interleaved, pitch 40
    __shared__ float Qs[32][PP];
    __shared__ float Vs[32][33];
    __shared__ float Tsh[4][32];
    __shared__ float Osh[4][32];
    __shared__ float a_sh[256];
    __shared__ int   s_last;

    const int g    = blockIdx.x;
    const int h    = blockIdx.y;
    const int tid  = threadIdx.x;
    const int w    = tid >> 5;
    const int lane = tid & 31;
    const int grp  = lane >> 2;
    const int tig  = lane & 3;
    const int hb   = h * 32;

    const int start = __ldg(&g_off[g]);
    const int end   = __ldg(&g_off[g + 1]);
    const int L     = end - start;

    const float4 z4 = make_float4(0.f, 0.f, 0.f, 0.f);
    float out_acc = 0.0f;

    for (int mc = 0; mc < L; mc += 32) {
        const int lm = min(32, L - mc);
        if (mc > 0) __syncthreads();       // prior Ks/Vs/Tsh readers done

        // stage K chunk (tf32, interleaved): slot tid -> row=tid>>2, c8=tid&3
        {
            int row = tid >> 2, c8 = tid & 3;
            float4 lo = z4, hi = z4;
            if (row < lm) {
                const float* src = &g_qkv[(start + mc + row) * QKV_LD + 256 + hb + c8 * 8];
                lo = *(const float4*)src;
                hi = *(const float4*)(src + 4);
            }
            float4 s0 = make_float4(to_tf32(lo.x), to_tf32(hi.x),
                                    to_tf32(lo.y), to_tf32(hi.y));
            float4 s1 = make_float4(to_tf32(lo.z), to_tf32(hi.z),
                                    to_tf32(lo.w), to_tf32(hi.w));
            *(float4*)&Ks[row][c8 * 8]     = s0;
            *(float4*)&Ks[row][c8 * 8 + 4] = s1;
        }
        // stage V chunk (plain fp32)
        #pragma unroll
        for (int it = 0; it < 2; it++) {
            int idx = tid + it * 128;
            int r   = idx >> 3;
            int c4  = idx & 7;
            float4 vv = (r < lm) ? *(const float4*)&g_qkv[(start + mc + r) * QKV_LD + 512 + hb + c4 * 4] : z4;
            Vs[r][c4 * 4 + 0] = vv.x; Vs[r][c4 * 4 + 1] = vv.y;
            Vs[r][c4 * 4 + 2] = vv.z; Vs[r][c4 * 4 + 3] = vv.w;
        }

        float T0 = 0.f, T1 = 0.f, T2 = 0.f, T3 = 0.f;   // m = grp, grp+8, grp+16, grp+24

        for (int nc = 0; nc < L; nc += 32) {
            const int ln = min(32, L - nc);
            if (nc > 0) __syncthreads();   // prior Qs readers done
            // stage Q chunk (tf32, interleaved)
            {
                int row = tid >> 2, c8 = tid & 3;
                float4 lo = z4, hi = z4;
                if (row < ln) {
                    const float* src = &g_qkv[(start + nc + row) * QKV_LD + hb + c8 * 8];
                    lo = *(const float4*)src;
                    hi = *(const float4*)(src + 4);
                }
                float4 s0 = make_float4(to_tf32(lo.x), to_tf32(hi.x),
                                        to_tf32(lo.y), to_tf32(hi.y));
                float4 s1 = make_float4(to_tf32(lo.z), to_tf32(hi.z),
                                        to_tf32(lo.w), to_tf32(hi.w));
                *(float4*)&Qs[row][c8 * 8]     = s0;
                *(float4*)&Qs[row][c8 * 8 + 4] = s1;
            }
            __syncthreads();

            // warp w: S cols [w*8, w*8+8), all 32 m-rows -> 2 C tiles
            float c[2][4] = {{0.f,0.f,0.f,0.f},{0.f,0.f,0.f,0.f}};
            #pragma unroll
            for (int ks = 0; ks < 4; ks++) {
                const int kp = ks * 8 + 2 * tig;
                float2 pB = *(const float2*)&Qs[w * 8 + grp][kp];
                unsigned bf[2];
                bf[0] = __float_as_uint(pB.x);
                bf[1] = __float_as_uint(pB.y);
                #pragma unroll
                for (int mt = 0; mt < 2; mt++) {
                    int rb = mt * 16 + grp;
                    float2 pA0 = *(const float2*)&Ks[rb    ][kp];
                    float2 pA1 = *(const float2*)&Ks[rb + 8][kp];
                    unsigned af[4];
                    af[0] = __float_as_uint(pA0.x);
                    af[1] = __float_as_uint(pA1.x);
                    af[2] = __float_as_uint(pA0.y);
                    af[3] = __float_as_uint(pA1.y);
                    mma_tf32(c[mt], af, bf);
                }
            }
            // silu + row sums: c0,c1 -> row (mt*16+grp); c2,c3 -> row (+8)
            #pragma unroll
            for (int mt = 0; mt < 2; mt++) {
                float s0 = silu_fast(c[mt][0]) + silu_fast(c[mt][1]);
                float s1 = silu_fast(c[mt][2]) + silu_fast(c[mt][3]);
                s0 += __shfl_xor_sync(0xffffffffu, s0, 1);
                s0 += __shfl_xor_sync(0xffffffffu, s0, 2);
                s1 += __shfl_xor_sync(0xffffffffu, s1, 1);
                s1 += __shfl_xor_sync(0xffffffffu, s1, 2);
                if (mt == 0) { T0 += s0; T1 += s1; }
                else         { T2 += s0; T3 += s1; }
            }
        }

        // combine T across warps (each warp has partials over its 8 n-cols)
        if (tig == 0) {
            Tsh[w][grp]      = T0;
            Tsh[w][grp + 8]  = T1;
            Tsh[w][grp + 16] = T2;
            Tsh[w][grp + 24] = T3;
        }
        __syncthreads();

        // AV: warp w handles m in [w*8, w*8+8)
        #pragma unroll
        for (int i = 0; i < 8; i++) {
            int m = w * 8 + i;
            float tm = Tsh[0][m] + Tsh[1][m] + Tsh[2][m] + Tsh[3][m];
            out_acc += tm * Vs[m][lane];
        }
    }

    __syncthreads();
    Osh[w][lane] = out_acc;
    __syncthreads();
    if (w == 0)
        g_segsum[g * 256 + hb + lane] =
            Osh[0][lane] + Osh[1][lane] + Osh[2][lane] + Osh[3][lane];

    // ---- last block of this group computes the output projection ----
    __threadfence();
    if (tid == 0) {
        int old = atomicAdd(&g_cnt[g], 1);
        s_last = (old == 7) ? 1 : 0;
    }
    __syncthreads();
    if (!s_last) return;

    __threadfence();    // acquire: make all 8 segsum slices visible
    {
        float2 s2 = *(const float2*)&g_segsum[g * 256 + tid * 2];
        a_sh[tid * 2]     = s2.x;
        a_sh[tid * 2 + 1] = s2.y;
    }
    __syncthreads();

    const float cnt = (float)L;
    float acc0 = 0.f, acc1 = 0.f;
    #pragma unroll 8
    for (int f = 0; f < 256; f++) {
        float av = a_sh[f];
        float2 w2 = *(const float2*)&g_wct[f * 256 + tid * 2];
        acc0 += av * w2.x;
        acc1 += av * w2.y;
    }
    float2 bc2  = *(const float2*)&g_bc[tid * 2];
    float2 bo22 = *(const float2*)&bo2[tid * 2];
    float r0 = acc0 + cnt * bc2.x + bo22.x;
    float r1 = acc1 + cnt * bc2.y + bo22.y;
    *(float2*)&out[g * 256 + tid * 2] = make_float2(silu(r0), silu(r1));
}

// ---------------------------------------------------------------------------
extern "C" void kernel_launch(void* const* d_in, const int* in_sizes, int n_in,
                              void* d_out, int out_size)
{
    const float* x    = (const float*)d_in[0];
    const int*   elem = (const int*)d_in[1];
    const int*   seg  = elem + N_ATOMS;        // elem_index[1]
    const float* Wq   = (const float*)d_in[2];
    const float* bq   = (const float*)d_in[3];
    const float* Wk   = (const float*)d_in[4];
    const float* bk   = (const float*)d_in[5];
    const float* Wv   = (const float*)d_in[6];
    const float* bv   = (const float*)d_in[7];
    const float* Wo1  = (const float*)d_in[8];
    const float* bo1  = (const float*)d_in[9];
    const float* Wo2  = (const float*)d_in[10];
    const float* bo2  = (const float*)d_in[11];
    float* out = (float*)d_out;

    k1<<<K1_BLOCKS, 128>>>(x, Wq, bq, Wk, bk, Wv, bv, Wo1, bo1, Wo2, seg);
    attn_kernel<<<dim3(NG, 8), 128>>>(bo2, out);
}

// round 16
// speedup vs baseline: 1.1848x; 1.0506x over previous
#include <cuda_runtime.h>
#include <math.h>

#define N_ATOMS 4096
#define NG      128
#define QKV_LD  768

// Scratch (no allocations allowed)
__device__ float g_qkv[N_ATOMS * QKV_LD];   // per row: [0:256)=Q [256:512)=K [512:768)=V
__device__ float g_wct[256 * 256];          // Wct[f][j] = (Wo2 @ Wo1)^T
__device__ float g_bc[256];                 // bc = Wo2 @ bo1
__device__ int   g_off[NG + 1];             // group start offsets (sorted seg ids)

__device__ __forceinline__ float to_tf32(float x) {
    asm("cvt.rna.tf32.f32 %0, %0;" : "+f"(x));
    return x;
}

__device__ __forceinline__ void mma_tf32(float c[4], const unsigned a[4], const unsigned b[2]) {
    asm volatile(
        "mma.sync.aligned.m16n8k8.row.col.f32.tf32.tf32.f32 "
        "{%0,%1,%2,%3}, {%4,%5,%6,%7}, {%8,%9}, {%0,%1,%2,%3};"
        : "+f"(c[0]), "+f"(c[1]), "+f"(c[2]), "+f"(c[3])
        : "r"(a[0]), "r"(a[1]), "r"(a[2]), "r"(a[3]), "r"(b[0]), "r"(b[1]));
}

__device__ __forceinline__ float silu(float v) {          // exact-ish (final layer)
    return __fdividef(v, 1.0f + __expf(-v));
}

__device__ __forceinline__ float silu_fast(float x) {     // 1 MUFU: x/2*(1+tanh(x/2))
    float h = 0.5f * x;
    float t;
    asm("tanh.approx.f32 %0, %1;" : "=f"(t) : "f"(h));
    return h + h * t;
}

// ---------------------------------------------------------------------------
// k1 mega-kernel (128 threads/block):  [R9 proven config, unchanged]
//   blocks [0,384)   : TF32 QKV projection, BM=128 BN=64 BK=32
//   blocks [384,416) : fp32 Wct[f][j] = sum_k Wo1[k][f] * Wo2[j][k]
//   blocks [416,424) : bc[j] = Wo2[j,:].bo1 ; block 416: g_off
// ---------------------------------------------------------------------------
#define PROJ_BLOCKS 384
#define WC_BLOCKS   32
#define K1_BLOCKS   (PROJ_BLOCKS + WC_BLOCKS + 8)
#define PP          40

__global__ __launch_bounds__(128) void k1(
        const float* __restrict__ x,
        const float* __restrict__ Wq, const float* __restrict__ bq,
        const float* __restrict__ Wk, const float* __restrict__ bk,
        const float* __restrict__ Wv, const float* __restrict__ bv,
        const float* __restrict__ Wo1, const float* __restrict__ bo1,
        const float* __restrict__ Wo2, const int* __restrict__ seg)
{
    __shared__ float sh[7680];
    const int bid = blockIdx.x;
    const int tid = threadIdx.x;

    if (bid < PROJ_BLOCKS) {
        float (*As)[PP] = (float(*)[PP])sh;              // [128][40]
        float (*Bs)[PP] = (float(*)[PP])(sh + 128 * PP); // [64][40]

        const int warp = tid >> 5;
        const int lane = tid & 31;
        const int grp  = lane >> 2;
        const int tig  = lane & 3;
        const int wm   = warp >> 1;
        const int wn   = warp & 1;

        const int n0 = (bid / 12) * 128;
        const int j0 = (bid % 12) * 64;
        const int sel = j0 >> 8;
        const float* __restrict__ W = (sel == 0) ? Wq : (sel == 1 ? Wk : Wv);
        const float* __restrict__ b = (sel == 0) ? bq : (sel == 1 ? bk : bv);
        const int jl = j0 & 255;

        float c[4][4][4] = {};

        for (int k0 = 0; k0 < 256; k0 += 32) {
            #pragma unroll
            for (int it = 0; it < 4; it++) {
                int lin = tid + it * 128;
                int row = lin >> 2;
                int c8  = lin & 3;
                const float* src = &x[(n0 + row) * 256 + k0 + c8 * 8];
                float4 lo = *(const float4*)src;
                float4 hi = *(const float4*)(src + 4);
                float4 s0 = make_float4(to_tf32(lo.x), to_tf32(hi.x),
                                        to_tf32(lo.y), to_tf32(hi.y));
                float4 s1 = make_float4(to_tf32(lo.z), to_tf32(hi.z),
                                        to_tf32(lo.w), to_tf32(hi.w));
                *(float4*)&As[row][c8 * 8]     = s0;
                *(float4*)&As[row][c8 * 8 + 4] = s1;
            }
            #pragma unroll
            for (int it = 0; it < 2; it++) {
                int lin = tid + it * 128;
                int row = lin >> 2;
                int c8  = lin & 3;
                const float* src = &W[(jl + row) * 256 + k0 + c8 * 8];
                float4 lo = *(const float4*)src;
                float4 hi = *(const float4*)(src + 4);
                float4 s0 = make_float4(to_tf32(lo.x), to_tf32(hi.x),
                                        to_tf32(lo.y), to_tf32(hi.y));
                float4 s1 = make_float4(to_tf32(lo.z), to_tf32(hi.z),
                                        to_tf32(lo.w), to_tf32(hi.w));
                *(float4*)&Bs[row][c8 * 8]     = s0;
                *(float4*)&Bs[row][c8 * 8 + 4] = s1;
            }
            __syncthreads();

            #pragma unroll
            for (int ks = 0; ks < 4; ks++) {
                const int kp = ks * 8 + 2 * tig;
                unsigned bf[4][2];
                #pragma unroll
                for (int nt = 0; nt < 4; nt++) {
                    float2 pB = *(const float2*)&Bs[wn * 32 + nt * 8 + grp][kp];
                    bf[nt][0] = __float_as_uint(pB.x);
                    bf[nt][1] = __float_as_uint(pB.y);
                }
                #pragma unroll
                for (int mt = 0; mt < 4; mt++) {
                    int rb = wm * 64 + mt * 16 + grp;
                    float2 pA0 = *(const float2*)&As[rb    ][kp];
                    float2 pA1 = *(const float2*)&As[rb + 8][kp];
                    unsigned af[4];
                    af[0] = __float_as_uint(pA0.x);
                    af[1] = __float_as_uint(pA1.x);
                    af[2] = __float_as_uint(pA0.y);
                    af[3] = __float_as_uint(pA1.y);
                    #pragma unroll
                    for (int nt = 0; nt < 4; nt++)
                        mma_tf32(c[mt][nt], af, bf[nt]);
                }
            }
            __syncthreads();
        }

        #pragma unroll
        for (int mt = 0; mt < 4; mt++) {
            int r0 = n0 + wm * 64 + mt * 16 + grp;
            int r1 = r0 + 8;
            #pragma unroll
            for (int nt = 0; nt < 4; nt++) {
                int jj  = j0 + wn * 32 + nt * 8 + tig * 2;
                int jlb = jl + wn * 32 + nt * 8 + tig * 2;
                float b0 = b[jlb], b1 = b[jlb + 1];
                *(float2*)&g_qkv[r0 * QKV_LD + jj] = make_float2(c[mt][nt][0] + b0, c[mt][nt][1] + b1);
                *(float2*)&g_qkv[r1 * QKV_LD + jj] = make_float2(c[mt][nt][2] + b0, c[mt][nt][3] + b1);
            }
        }
    } else if (bid < PROJ_BLOCKS + WC_BLOCKS) {
        float (*As)[36] = (float(*)[36])sh;
        float (*Bs)[68] = (float(*)[68])(sh + 32 * 36);

        const int t  = bid - PROJ_BLOCKS;
        const int f0 = (t >> 2) * 32;
        const int j0 = (t & 3) * 64;
        const int ti = tid >> 3;
        const int tj = tid & 7;

        float acc[2][8] = {};

        for (int k0 = 0; k0 < 256; k0 += 32) {
            #pragma unroll
            for (int it = 0; it < 2; it++) {
                int lin = tid + it * 128;
                int kk = lin >> 3;
                int fq = lin & 7;
                float4 a = *(const float4*)&Wo1[(k0 + kk) * 256 + f0 + fq * 4];
                *(float4*)&As[kk][fq * 4] = a;
            }
            #pragma unroll
            for (int it = 0; it < 4; it++) {
                int lin = tid + it * 128;
                int jj = lin >> 3;
                int kq = lin & 7;
                float4 w = *(const float4*)&Wo2[(j0 + jj) * 256 + k0 + kq * 4];
                Bs[kq * 4 + 0][jj] = w.x;
                Bs[kq * 4 + 1][jj] = w.y;
                Bs[kq * 4 + 2][jj] = w.z;
                Bs[kq * 4 + 3][jj] = w.w;
            }
            __syncthreads();
            #pragma unroll
            for (int kk = 0; kk < 32; kk++) {
                float2 a2 = *(const float2*)&As[kk][ti * 2];
                float4 b4a = *(const float4*)&Bs[kk][tj * 8];
                float4 b4b = *(const float4*)&Bs[kk][tj * 8 + 4];
                acc[0][0] += a2.x * b4a.x; acc[0][1] += a2.x * b4a.y;
                acc[0][2] += a2.x * b4a.z; acc[0][3] += a2.x * b4a.w;
                acc[0][4] += a2.x * b4b.x; acc[0][5] += a2.x * b4b.y;
                acc[0][6] += a2.x * b4b.z; acc[0][7] += a2.x * b4b.w;
                acc[1][0] += a2.y * b4a.x; acc[1][1] += a2.y * b4a.y;
                acc[1][2] += a2.y * b4a.z; acc[1][3] += a2.y * b4a.w;
                acc[1][4] += a2.y * b4b.x; acc[1][5] += a2.y * b4b.y;
                acc[1][6] += a2.y * b4b.z; acc[1][7] += a2.y * b4b.w;
            }
            __syncthreads();
        }
        #pragma unroll
        for (int u = 0; u < 2; u++)
            #pragma unroll
            for (int v = 0; v < 8; v++)
                g_wct[(f0 + ti * 2 + u) * 256 + j0 + tj * 8 + v] = acc[u][v];
    } else {
        const int bb   = bid - PROJ_BLOCKS - WC_BLOCKS;   // 0..7
        const int w    = tid >> 5;
        const int lane = tid & 31;
        #pragma unroll
        for (int u = 0; u < 8; u++) {
            int j = bb * 32 + w * 8 + u;
            float s = 0.0f;
            #pragma unroll
            for (int kc = 0; kc < 8; kc++) {
                int k = kc * 32 + lane;
                s += Wo2[j * 256 + k] * bo1[k];
            }
            #pragma unroll
            for (int off = 16; off; off >>= 1)
                s += __shfl_xor_sync(0xffffffffu, s, off);
            if (lane == 0) g_bc[j] = s;
        }
        if (bb == 0) {
            int g = tid;          // 0..127
            int lo = 0, hi = N_ATOMS;
            while (lo < hi) { int mid = (lo + hi) >> 1; if (seg[mid] < g) lo = mid + 1; else hi = mid; }
            g_off[g] = lo;
            if (tid == 0) g_off[NG] = N_ATOMS;
        }
    }
}

// ---------------------------------------------------------------------------
// Whole-group MMA attention + fused output projection.
// Block = group; 256 threads = 8 warps, warp w = head w (owns its full S tile).
// K/Q staged tf32-interleaved, V plain, all head-major [8][32][40] (per-head
// pitch 40: conflict-free frags, aligned float4 stores). Typical group
// (L<=32) runs ONE barrier in the attention body. No atomics, no counters.
//   warp w, per (mc,nc) chunk pair:  S(32x32) = K.Q^T  (2mt x 4nt x 4ks mma)
//   T[m] += row sums of silu(S) via C-layout + 2 shfl_xor
//   AV: out[d] += T[m]*V[m][d];  then block-local projection from smem.
// ---------------------------------------------------------------------------
#define HSTRIDE 1280          // 32 rows * pitch 40 per head
#define ATTN_SMEM ((3 * 8 * HSTRIDE + 256) * 4)

__global__ __launch_bounds__(256) void attn_kernel(
        const float* __restrict__ bo2, float* __restrict__ out)
{
    extern __shared__ float dsh[];
    float* Ks  = dsh;                       // [8][32][40] tf32 interleaved
    float* Qs  = dsh + 8 * HSTRIDE;         // [8][32][40] tf32 interleaved
    float* Vs  = dsh + 16 * HSTRIDE;        // [8][32][40] plain fp32
    float* a_sh = dsh + 24 * HSTRIDE;       // [256] segsum row

    const int g    = blockIdx.x;
    const int tid  = threadIdx.x;
    const int w    = tid >> 5;              // head
    const int lane = tid & 31;
    const int grp  = lane >> 2;
    const int tig  = lane & 3;
    const int KB   = w * HSTRIDE;

    const int start = __ldg(&g_off[g]);
    const int end   = __ldg(&g_off[g + 1]);
    const int L     = end - start;

    const float4 z4 = make_float4(0.f, 0.f, 0.f, 0.f);
    float out_acc = 0.0f;

    for (int mc = 0; mc < L; mc += 32) {
        const int lm = min(32, L - mc);
        if (mc > 0) __syncthreads();        // prior Ks/Qs/Vs readers done

        // stage K (tf32 interleaved, all heads): 1024 8-float slots
        #pragma unroll
        for (int it = 0; it < 4; it++) {
            int s   = tid + it * 256;       // 0..1023
            int row = s >> 5;               // 0..31
            int c8  = s & 31;               // 8-float group across 256 cols
            float4 lo = z4, hi = z4;
            if (row < lm) {
                const float* src = &g_qkv[(start + mc + row) * QKV_LD + 256 + c8 * 8];
                lo = *(const float4*)src;
                hi = *(const float4*)(src + 4);
            }
            float* dst = &Ks[(c8 >> 2) * HSTRIDE + row * 40 + (c8 & 3) * 8];
            ((float4*)dst)[0] = make_float4(to_tf32(lo.x), to_tf32(hi.x),
                                            to_tf32(lo.y), to_tf32(hi.y));
            ((float4*)dst)[1] = make_float4(to_tf32(lo.z), to_tf32(hi.z),
                                            to_tf32(lo.w), to_tf32(hi.w));
        }
        // stage V (plain, all heads): 2048 float4 slots
        #pragma unroll
        for (int it = 0; it < 8; it++) {
            int s   = tid + it * 256;       // 0..2047
            int row = s >> 6;               // 0..31
            int c4  = s & 63;
            float4 v = (row < lm) ? *(const float4*)&g_qkv[(start + mc + row) * QKV_LD + 512 + c4 * 4] : z4;
            *(float4*)&Vs[(c4 >> 3) * HSTRIDE + row * 40 + (c4 & 7) * 4] = v;
        }

        float T0 = 0.f, T1 = 0.f, T2 = 0.f, T3 = 0.f;   // m = grp, +8, +16, +24

        for (int nc = 0; nc < L; nc += 32) {
            const int ln = min(32, L - nc);
            if (nc > 0) __syncthreads();    // prior Qs readers done
            // stage Q (tf32 interleaved, all heads)
            #pragma unroll
            for (int it = 0; it < 4; it++) {
                int s   = tid + it * 256;
                int row = s >> 5;
                int c8  = s & 31;
                float4 lo = z4, hi = z4;
                if (row < ln) {
                    const float* src = &g_qkv[(start + nc + row) * QKV_LD + c8 * 8];
                    lo = *(const float4*)src;
                    hi = *(const float4*)(src + 4);
                }
                float* dst = &Qs[(c8 >> 2) * HSTRIDE + row * 40 + (c8 & 3) * 8];
                ((float4*)dst)[0] = make_float4(to_tf32(lo.x), to_tf32(hi.x),
                                                to_tf32(lo.y), to_tf32(hi.y));
                ((float4*)dst)[1] = make_float4(to_tf32(lo.z), to_tf32(hi.z),
                                                to_tf32(lo.w), to_tf32(hi.w));
            }
            __syncthreads();                // K/V (first iter) + Q staged

            // warp w: full 32x32 S for head w = 4 n-tiles x 2 m-tiles x 4 ks
            #pragma unroll
            for (int nt = 0; nt < 4; nt++) {
                float c[2][4] = {{0.f,0.f,0.f,0.f},{0.f,0.f,0.f,0.f}};
                #pragma unroll
                for (int ks = 0; ks < 4; ks++) {
                    const int kp = ks * 8 + 2 * tig;
                    float2 pB = *(const float2*)&Qs[KB + (nt * 8 + grp) * 40 + kp];
                    unsigned bf[2];
                    bf[0] = __float_as_uint(pB.x);
                    bf[1] = __float_as_uint(pB.y);
                    #pragma unroll
                    for (int mt = 0; mt < 2; mt++) {
                        int rb = mt * 16 + grp;
                        float2 pA0 = *(const float2*)&Ks[KB + rb * 40 + kp];
                        float2 pA1 = *(const float2*)&Ks[KB + (rb + 8) * 40 + kp];
                        unsigned af[4];
                        af[0] = __float_as_uint(pA0.x);
                        af[1] = __float_as_uint(pA1.x);
                        af[2] = __float_as_uint(pA0.y);
                        af[3] = __float_as_uint(pA1.y);
                        mma_tf32(c[mt], af, bf);
                    }
                }
                // silu + row sums for this n-tile
                #pragma unroll
                for (int mt = 0; mt < 2; mt++) {
                    float s0 = silu_fast(c[mt][0]) + silu_fast(c[mt][1]);
                    float s1 = silu_fast(c[mt][2]) + silu_fast(c[mt][3]);
                    s0 += __shfl_xor_sync(0xffffffffu, s0, 1);
                    s0 += __shfl_xor_sync(0xffffffffu, s0, 2);
                    s1 += __shfl_xor_sync(0xffffffffu, s1, 1);
                    s1 += __shfl_xor_sync(0xffffffffu, s1, 2);
                    if (mt == 0) { T0 += s0; T1 += s1; }
                    else         { T2 += s0; T3 += s1; }
                }
            }
        }

        // AV within warp: broadcast T[m] from quad m, read V row m
        #pragma unroll
        for (int i = 0; i < 8; i++) {
            float tm0 = __shfl_sync(0xffffffffu, T0, i * 4);
            float tm1 = __shfl_sync(0xffffffffu, T1, i * 4);
            float tm2 = __shfl_sync(0xffffffffu, T2, i * 4);
            float tm3 = __shfl_sync(0xffffffffu, T3, i * 4);
            out_acc += tm0 * Vs[KB + (i     ) * 40 + lane];
            out_acc += tm1 * Vs[KB + (i +  8) * 40 + lane];
            out_acc += tm2 * Vs[KB + (i + 16) * 40 + lane];
            out_acc += tm3 * Vs[KB + (i + 24) * 40 + lane];
        }
    }

    // segsum row lives in this block
    if (L > 0) __syncthreads();
    a_sh[w * 32 + lane] = out_acc;
    __syncthreads();

    // fused output projection: thread = column j
    const float cnt = (float)L;
    float acc = 0.0f;
    #pragma unroll 8
    for (int f = 0; f < 256; f++)
        acc += a_sh[f] * g_wct[f * 256 + tid];

    out[g * 256 + tid] = silu(acc + cnt * g_bc[tid] + bo2[tid]);
}

// ---------------------------------------------------------------------------
extern "C" void kernel_launch(void* const* d_in, const int* in_sizes, int n_in,
                              void* d_out, int out_size)
{
    const float* x    = (const float*)d_in[0];
    const int*   elem = (const int*)d_in[1];
    const int*   seg  = elem + N_ATOMS;        // elem_index[1]
    const float* Wq   = (const float*)d_in[2];
    const float* bq   = (const float*)d_in[3];
    const float* Wk   = (const float*)d_in[4];
    const float* bk   = (const float*)d_in[5];
    const float* Wv   = (const float*)d_in[6];
    const float* bv   = (const float*)d_in[7];
    const float* Wo1  = (const float*)d_in[8];
    const float* bo1  = (const float*)d_in[9];
    const float* Wo2  = (const float*)d_in[10];
    const float* bo2  = (const float*)d_in[11];
    float* out = (float*)d_out;

    cudaFuncSetAttribute(attn_kernel, cudaFuncAttributeMaxDynamicSharedMemorySize, ATTN_SMEM);

    k1<<<K1_BLOCKS, 128>>>(x, Wq, bq, Wk, bk, Wv, bv, Wo1, bo1, Wo2, seg);
    attn_kernel<<<NG, 256, ATTN_SMEM>>>(bo2, out);
}